// round 10
// baseline (speedup 1.0000x reference)
#include <cuda_runtime.h>
#include <cuda_fp16.h>
#include <cstdint>
#include <cstddef>

// FixedGraphAttentionLayer: bs=4, L=20000, D=16, Fin=Fout=128
//   y = x @ W per node (linear rewrite), y stored fp16.
//   e[b,l,d] = s1[adj[b,l,d]] + s2[adj[b,l,0]]  (scores from fp32 accumulators)
// prep = W fragment pre-pack (wide grid).
// k1 = HMMA GEMM + fused scores; B frags read from global (L1-hot), 16 KB smem,
//      nt-loop split in two halves to cut registers -> higher occupancy.
// k2 = in-block adj dtype detect + softmax + LDG.128 gather + elu. (measured 39us)

#define LRELU_ALPHA 0.2f
static constexpr int BS = 4;
static constexpr int L  = 20000;
static constexpr int D  = 16;
static constexpr int F  = 128;
static constexpr int NROWS = BS * L;   // 80000

__device__ __align__(16) __half g_yh[(size_t)NROWS * F];   // 20.5 MB
__device__ float g_s1[NROWS];
__device__ float g_s2[NROWS];
__device__ __align__(16) uint2 g_Bpack[8 * 16 * 32];       // [kc][nt][lane], 32 KB

// ---------------------------------------------------------------------------
// Prep (32 blocks x 128 threads; one fragment element per thread):
// pack W (fp32 [k=128][n=128]) into mma.m16n8k16 B fragments (fp16).
//   b0 = {W[k0][n], W[k0+1][n]}, b1 = {W[k0+8][n], W[k0+9][n]},
//   k0 = 16*kc + tg*2, n = 8*nt + g   (g = lane>>2, tg = lane&3)
// ---------------------------------------------------------------------------
__global__ void prep_kernel(const float* __restrict__ W)
{
    const int e = blockIdx.x * 128 + threadIdx.x;  // 0..4095
    const int kc = e >> 9, nt = (e >> 5) & 15, lane = e & 31;
    const int g = lane >> 2, tg = lane & 3;
    const int n = nt * 8 + g, k0 = kc * 16 + tg * 2;
    __half2 b0 = __floats2half2_rn(W[k0 * F + n],       W[(k0 + 1) * F + n]);
    __half2 b1 = __floats2half2_rn(W[(k0 + 8) * F + n], W[(k0 + 9) * F + n]);
    uint2 u;
    u.x = *reinterpret_cast<unsigned*>(&b0);
    u.y = *reinterpret_cast<unsigned*>(&b1);
    g_Bpack[e] = u;
}

// ---------------------------------------------------------------------------
// Kernel 1: y = x @ W via HMMA + fused scores. 128 threads, 64 rows/block.
// Warp w owns rows w*16..w*16+15. B fragments loaded from g_Bpack (global,
// L1/L2-hot). nt processed in two halves of 8 (acc regs halved).
// x tile fp16 in smem, XOR swizzle (r&7)*4 for conflict-free frag LDS.
// ---------------------------------------------------------------------------
__global__ __launch_bounds__(128)
void gemm_scores_kernel(const float* __restrict__ x,
                        const float* __restrict__ a)
{
    __shared__ __half2 Xs[64 * 64];   // 16 KB: x tile, later y restage scratch

    const int tid  = threadIdx.x;
    const int lane = tid & 31;
    const int w    = tid >> 5;
    const int g    = lane >> 2;       // 0..7
    const int tg   = lane & 3;        // 0..3
    const int rowbase = blockIdx.x * 64;

    // x tile (64x128 fp32) -> fp16 swizzled smem
    #pragma unroll
    for (int j = tid; j < 4096; j += 128) {
        const int r = j >> 6, kh2 = j & 63;
        float2 v = *(const float2*)(x + (size_t)(rowbase + r) * F + kh2 * 2);
        Xs[r * 64 + (kh2 ^ ((r & 7) * 4))] = __floats2half2_rn(v.x, v.y);
    }
    __syncthreads();

    // A fragments for this warp's 16 rows, all 8 k-chunks (32 regs)
    unsigned Areg[8][4];
    {
        const int r0 = w * 16 + g, r1 = r0 + 8;
        const int s  = g * 4;
        #pragma unroll
        for (int kc = 0; kc < 8; kc++) {
            const int kl = kc * 8 + tg, kh = kl + 4;
            Areg[kc][0] = *reinterpret_cast<unsigned*>(&Xs[r0 * 64 + (kl ^ s)]);
            Areg[kc][1] = *reinterpret_cast<unsigned*>(&Xs[r1 * 64 + (kl ^ s)]);
            Areg[kc][2] = *reinterpret_cast<unsigned*>(&Xs[r0 * 64 + (kh ^ s)]);
            Areg[kc][3] = *reinterpret_cast<unsigned*>(&Xs[r1 * 64 + (kh ^ s)]);
        }
    }
    __syncthreads();   // all A-frag reads done before Xs is reused as scratch

    float p1a = 0.f, p1b = 0.f, p2a = 0.f, p2b = 0.f;

    #pragma unroll 1
    for (int hf = 0; hf < 2; hf++) {
        float acc[8][4];
        #pragma unroll
        for (int nt = 0; nt < 8; nt++)
            #pragma unroll
            for (int q = 0; q < 4; q++) acc[nt][q] = 0.f;

        #pragma unroll
        for (int nt = 0; nt < 8; nt++) {
            #pragma unroll
            for (int kc = 0; kc < 8; kc++) {
                const uint2 b = __ldg(&g_Bpack[kc * 512 + (hf * 8 + nt) * 32 + lane]);
                asm volatile(
                    "mma.sync.aligned.m16n8k16.row.col.f32.f16.f16.f32 "
                    "{%0,%1,%2,%3}, {%4,%5,%6,%7}, {%8,%9}, {%0,%1,%2,%3};"
                    : "+f"(acc[nt][0]), "+f"(acc[nt][1]), "+f"(acc[nt][2]), "+f"(acc[nt][3])
                    : "r"(Areg[kc][0]), "r"(Areg[kc][1]), "r"(Areg[kc][2]), "r"(Areg[kc][3]),
                      "r"(b.x), "r"(b.y));
            }
        }

        // score partials from fp32 accumulators (cols hf*64 + nt*8 + tg*2 ..)
        #pragma unroll
        for (int nt = 0; nt < 8; nt++) {
            const float2 a1p = *(const float2*)(a + hf * 64 + nt * 8 + tg * 2);
            const float2 a2p = *(const float2*)(a + F + hf * 64 + nt * 8 + tg * 2);
            p1a += acc[nt][0] * a1p.x + acc[nt][1] * a1p.y;
            p1b += acc[nt][2] * a1p.x + acc[nt][3] * a1p.y;
            p2a += acc[nt][0] * a2p.x + acc[nt][1] * a2p.y;
            p2b += acc[nt][2] * a2p.x + acc[nt][3] * a2p.y;
        }

        // restage this half's y cols (hf*64..hf*64+63) into Xs, then store
        __syncthreads();   // prior phase's cross-warp Xs reads complete
        {
            const int r0 = w * 16 + g;
            const int s  = g * 4;
            #pragma unroll
            for (int nt = 0; nt < 8; nt++) {
                const int c = nt * 4 + tg;          // 0..31 half2 within half
                Xs[r0 * 64 + hf * 32 + (c ^ s)]       = __floats2half2_rn(acc[nt][0], acc[nt][1]);
                Xs[(r0 + 8) * 64 + hf * 32 + (c ^ s)] = __floats2half2_rn(acc[nt][2], acc[nt][3]);
            }
        }
        __syncthreads();
        {
            const int r    = tid >> 1;              // 2 threads per row
            const int s    = (r & 7) * 4;
            const int base = (tid & 1) * 16;        // half2 offset within 32
            __half* dst = g_yh + (size_t)(rowbase + r) * F + hf * 64 + base * 2;
            #pragma unroll
            for (int j = 0; j < 4; j++) {
                uint4 v = *reinterpret_cast<uint4*>(&Xs[r * 64 + hf * 32 + ((base + j * 4) ^ s)]);
                *reinterpret_cast<uint4*>(dst + j * 8) = v;
            }
        }
    }

    // final score reduction over the tg quad + store
    #pragma unroll
    for (int o = 1; o <= 2; o <<= 1) {
        p1a += __shfl_xor_sync(0xffffffffu, p1a, o);
        p1b += __shfl_xor_sync(0xffffffffu, p1b, o);
        p2a += __shfl_xor_sync(0xffffffffu, p2a, o);
        p2b += __shfl_xor_sync(0xffffffffu, p2b, o);
    }
    if (tg == 0) {
        const int r = rowbase + w * 16 + g;
        g_s1[r] = p1a;  g_s2[r] = p2a;
        g_s1[r + 8] = p1b;  g_s2[r + 8] = p2b;
    }
}

// ---------------------------------------------------------------------------
// Kernel 2 (measured 39us): one warp per node. In-block adj dtype detect,
// softmax(leaky_relu(e)), LDG.128 gather (half-warps on alternate rows), elu.
// ---------------------------------------------------------------------------
__global__ __launch_bounds__(256)
void attn_out_kernel(const int* __restrict__ adj32,
                     float* __restrict__ out)
{
    __shared__ int s_is64;
    const int tid  = threadIdx.x;
    const int lane = tid & 31;

    // detect: adj is int64 iff odd 32-bit words are all zero (values < 2^31)
    if (tid < 32) {
        const int bad = (adj32[2 * tid + 1] != 0) | (adj32[2 * tid + 65] != 0);
        const unsigned mm = __ballot_sync(0xffffffffu, bad);
        if (tid == 0) s_is64 = (mm == 0u);
    }
    __syncthreads();
    const int is64 = s_is64;

    const int warp = (blockIdx.x * blockDim.x + tid) >> 5;   // < NROWS by construction
    const int b = warp / L;
    const size_t nodebase = (size_t)b * L;

    int   idx = 0;
    float e   = -INFINITY;
    if (lane < D) {
        const size_t ei = (size_t)warp * D + lane;
        int raw;
        if (is64) {
            long long v = ((const long long*)adj32)[ei];   // single LDG.64
            raw = (int)v;
        } else {
            raw = adj32[ei];
        }
        raw = raw < 0 ? 0 : (raw >= L ? L - 1 : raw); // defensive clamp
        idx = raw;
        e   = g_s1[nodebase + idx];
    }
    const int idx0 = __shfl_sync(0xffffffffu, idx, 0);
    const float s2v = g_s2[nodebase + idx0];
    if (lane < D) {
        e += s2v;
        e = (e >= 0.f) ? e : LRELU_ALPHA * e;
    }

    float m = e;
    #pragma unroll
    for (int o = 16; o > 0; o >>= 1) m = fmaxf(m, __shfl_xor_sync(0xffffffffu, m, o));
    float p = (lane < D) ? __expf(e - m) : 0.f;
    float s = p;
    #pragma unroll
    for (int o = 16; o > 0; o >>= 1) s += __shfl_xor_sync(0xffffffffu, s, o);
    const float attn = p / s;

    // gather: 8 x LDG.128 per warp (2 rows per iteration via half-warps)
    const int li = lane & 15;
    const int h  = lane >> 4;
    const __half* yb = g_yh + nodebase * F;
    float acc[8];
    #pragma unroll
    for (int j = 0; j < 8; j++) acc[j] = 0.f;

    #pragma unroll
    for (int it = 0; it < 8; it++) {
        const int   d  = 2 * it + h;
        const int   id = __shfl_sync(0xffffffffu, idx,  d);
        const float wt = __shfl_sync(0xffffffffu, attn, d);
        uint4 raw = *(const uint4*)(yb + (size_t)id * F + li * 8);
        const __half2* hh = reinterpret_cast<const __half2*>(&raw);
        #pragma unroll
        for (int j = 0; j < 4; j++) {
            float2 f2 = __half22float2(hh[j]);
            acc[2 * j]     += wt * f2.x;
            acc[2 * j + 1] += wt * f2.y;
        }
    }
    #pragma unroll
    for (int j = 0; j < 8; j++)
        acc[j] += __shfl_xor_sync(0xffffffffu, acc[j], 16);

    // elu (alpha=1) on the 4 values this lane writes: cols li*8 + h*4 + 0..3
    float4 o4;
    o4.x = acc[h * 4 + 0]; o4.y = acc[h * 4 + 1];
    o4.z = acc[h * 4 + 2]; o4.w = acc[h * 4 + 3];
    o4.x = o4.x > 0.f ? o4.x : (__expf(o4.x) - 1.f);
    o4.y = o4.y > 0.f ? o4.y : (__expf(o4.y) - 1.f);
    o4.z = o4.z > 0.f ? o4.z : (__expf(o4.z) - 1.f);
    o4.w = o4.w > 0.f ? o4.w : (__expf(o4.w) - 1.f);

    *(float4*)(out + (size_t)warp * F + li * 8 + h * 4) = o4;
}

// ---------------------------------------------------------------------------
extern "C" void kernel_launch(void* const* d_in, const int* in_sizes, int n_in,
                              void* d_out, int out_size)
{
    //   x: 10,240,000 f32 | adj: 1,280,000 (i32 or i64) | W: 16,384 f32 | a: 256 f32
    const float* x   = nullptr;
    const int*   adj = nullptr;
    const float* W   = nullptr;
    const float* a   = nullptr;
    for (int i = 0; i < n_in; i++) {
        switch (in_sizes[i]) {
            case NROWS * F: x   = (const float*)d_in[i]; break;
            case NROWS * D: adj = (const int*)d_in[i];   break;
            case F * F:     W   = (const float*)d_in[i]; break;
            case 2 * F:     a   = (const float*)d_in[i]; break;
            default: break;
        }
    }
    float* out = (float*)d_out;

    prep_kernel<<<32, 128>>>(W);
    gemm_scores_kernel<<<NROWS / 64, 128>>>(x, a);
    attn_out_kernel<<<(NROWS * 32) / 256, 256>>>(adj, out);
}

// round 11
// speedup vs baseline: 1.1758x; 1.1758x over previous
#include <cuda_runtime.h>
#include <cuda_fp16.h>
#include <cstdint>
#include <cstddef>

// FixedGraphAttentionLayer: bs=4, L=20000, D=16, Fin=Fout=128
//   y = x @ W per node (linear rewrite), y stored fp16.
//   e[b,l,d] = s1[adj[b,l,d]] + s2[adj[b,l,0]]  (scores from fp32 accumulators)
// prep = W fragment pre-pack (wide grid).
// k1 = HMMA GEMM + fused scores; Bs in smem (R7 layout), A-fragments loaded
//      DIRECTLY from global x into registers (no x smem staging, no bars).
// k2 = in-block adj dtype detect + softmax + LDG.128 gather + elu (measured 39us).

#define LRELU_ALPHA 0.2f
static constexpr int BS = 4;
static constexpr int L  = 20000;
static constexpr int D  = 16;
static constexpr int F  = 128;
static constexpr int NROWS = BS * L;   // 80000

__device__ __align__(16) __half g_yh[(size_t)NROWS * F];   // 20.5 MB
__device__ float g_s1[NROWS];
__device__ float g_s2[NROWS];
__device__ __align__(16) uint2 g_Bpack[8 * 16 * 32];       // [kc][nt][lane], 32 KB

// ---------------------------------------------------------------------------
// Prep (32 blocks x 128 threads; one fragment element per thread):
// pack W (fp32 [k=128][n=128]) into mma.m16n8k16 B fragments (fp16).
//   b0 = {W[k0][n], W[k0+1][n]}, b1 = {W[k0+8][n], W[k0+9][n]},
//   k0 = 16*kc + tg*2, n = 8*nt + g   (g = lane>>2, tg = lane&3)
// ---------------------------------------------------------------------------
__global__ void prep_kernel(const float* __restrict__ W)
{
    const int e = blockIdx.x * 128 + threadIdx.x;  // 0..4095
    const int kc = e >> 9, nt = (e >> 5) & 15, lane = e & 31;
    const int g = lane >> 2, tg = lane & 3;
    const int n = nt * 8 + g, k0 = kc * 16 + tg * 2;
    __half2 b0 = __floats2half2_rn(W[k0 * F + n],       W[(k0 + 1) * F + n]);
    __half2 b1 = __floats2half2_rn(W[(k0 + 8) * F + n], W[(k0 + 9) * F + n]);
    uint2 u;
    u.x = *reinterpret_cast<unsigned*>(&b0);
    u.y = *reinterpret_cast<unsigned*>(&b1);
    g_Bpack[e] = u;
}

// ---------------------------------------------------------------------------
// Kernel 1: y = x @ W via HMMA + fused scores. 128 threads, 64 rows/block.
// Warp w owns rows w*16..w*16+15, all 128 cols (16 n-tiles x 8 k-chunks).
// A fragments loaded straight from global x (each element exactly once),
// converted to fp16 in registers. B fragments from Bs smem (R7 layout).
// Xs smem (16 KB) used only for the y-restage epilogue.
// ---------------------------------------------------------------------------
__global__ __launch_bounds__(128)
void gemm_scores_kernel(const float* __restrict__ x,
                        const float* __restrict__ a)
{
    __shared__ __half2 Xs[64 * 64];   // 16 KB: y restage scratch only
    __shared__ uint2   Bs[4096];      // 32 KB: [kc][nt][lane]

    const int tid  = threadIdx.x;
    const int lane = tid & 31;
    const int w    = tid >> 5;
    const int g    = lane >> 2;       // 0..7
    const int tg   = lane & 3;        // 0..3
    const int rowbase = blockIdx.x * 64;

    // copy B fragments (32 KB) global -> smem, coalesced
    {
        const uint4* src = (const uint4*)g_Bpack;
        uint4*       dst = (uint4*)Bs;
        #pragma unroll
        for (int i = tid; i < 2048; i += 128) dst[i] = src[i];
    }

    // A fragments: direct global loads (32 x LDG.64 per thread), pack to fp16.
    //   a0={x[r0][k0],x[r0][k0+1]}, a1=row r1, a2=cols +8, a3=r1 cols +8
    //   k0 = kc*16 + tg*2, r0 = rowbase + w*16 + g, r1 = r0 + 8
    unsigned Areg[8][4];
    {
        const float* xr0 = x + (size_t)(rowbase + w * 16 + g) * F + tg * 2;
        const float* xr1 = xr0 + 8 * F;
        #pragma unroll
        for (int kc = 0; kc < 8; kc++) {
            float2 v0 = *(const float2*)(xr0 + kc * 16);
            float2 v1 = *(const float2*)(xr1 + kc * 16);
            float2 v2 = *(const float2*)(xr0 + kc * 16 + 8);
            float2 v3 = *(const float2*)(xr1 + kc * 16 + 8);
            __half2 h0 = __floats2half2_rn(v0.x, v0.y);
            __half2 h1 = __floats2half2_rn(v1.x, v1.y);
            __half2 h2 = __floats2half2_rn(v2.x, v2.y);
            __half2 h3 = __floats2half2_rn(v3.x, v3.y);
            Areg[kc][0] = *reinterpret_cast<unsigned*>(&h0);
            Areg[kc][1] = *reinterpret_cast<unsigned*>(&h1);
            Areg[kc][2] = *reinterpret_cast<unsigned*>(&h2);
            Areg[kc][3] = *reinterpret_cast<unsigned*>(&h3);
        }
    }
    __syncthreads();   // Bs visible to all warps

    float acc[16][4];
    #pragma unroll
    for (int nt = 0; nt < 16; nt++)
        #pragma unroll
        for (int q = 0; q < 4; q++) acc[nt][q] = 0.f;

    #pragma unroll
    for (int nt = 0; nt < 16; nt++) {
        #pragma unroll
        for (int kc = 0; kc < 8; kc++) {
            const uint2 b = Bs[kc * 512 + nt * 32 + lane];
            asm volatile(
                "mma.sync.aligned.m16n8k16.row.col.f32.f16.f16.f32 "
                "{%0,%1,%2,%3}, {%4,%5,%6,%7}, {%8,%9}, {%0,%1,%2,%3};"
                : "+f"(acc[nt][0]), "+f"(acc[nt][1]), "+f"(acc[nt][2]), "+f"(acc[nt][3])
                : "r"(Areg[kc][0]), "r"(Areg[kc][1]), "r"(Areg[kc][2]), "r"(Areg[kc][3]),
                  "r"(b.x), "r"(b.y));
        }
    }

    // scores from fp32 accumulators: rows g (p1a/p2a) and g+8 (p1b/p2b)
    float p1a = 0.f, p1b = 0.f, p2a = 0.f, p2b = 0.f;
    #pragma unroll
    for (int nt = 0; nt < 16; nt++) {
        const float2 a1p = *(const float2*)(a + nt * 8 + tg * 2);
        const float2 a2p = *(const float2*)(a + F + nt * 8 + tg * 2);
        p1a += acc[nt][0] * a1p.x + acc[nt][1] * a1p.y;
        p1b += acc[nt][2] * a1p.x + acc[nt][3] * a1p.y;
        p2a += acc[nt][0] * a2p.x + acc[nt][1] * a2p.y;
        p2b += acc[nt][2] * a2p.x + acc[nt][3] * a2p.y;
    }
    #pragma unroll
    for (int o = 1; o <= 2; o <<= 1) {   // reduce over tg quad (lanes g*4..g*4+3)
        p1a += __shfl_xor_sync(0xffffffffu, p1a, o);
        p1b += __shfl_xor_sync(0xffffffffu, p1b, o);
        p2a += __shfl_xor_sync(0xffffffffu, p2a, o);
        p2b += __shfl_xor_sync(0xffffffffu, p2b, o);
    }
    if (tg == 0) {
        const int r = rowbase + w * 16 + g;
        g_s1[r] = p1a;  g_s2[r] = p2a;
        g_s1[r + 8] = p1b;  g_s2[r + 8] = p2b;
    }

    // stage y (fp16) into Xs (first use of Xs; warps write disjoint rows),
    // then coalesced 16B stores
    {
        const int r0 = w * 16 + g;
        const int s  = g * 4;
        #pragma unroll
        for (int nt = 0; nt < 16; nt++) {
            const int c = nt * 4 + tg;
            Xs[r0 * 64 + (c ^ s)]       = __floats2half2_rn(acc[nt][0], acc[nt][1]);
            Xs[(r0 + 8) * 64 + (c ^ s)] = __floats2half2_rn(acc[nt][2], acc[nt][3]);
        }
    }
    __syncthreads();
    {
        const int r = tid >> 1;                 // 2 threads per row
        const int s = (r & 7) * 4;
        const int base = (tid & 1) * 32;        // half2 offset
        __half* dst = g_yh + (size_t)(rowbase + r) * F + base * 2;
        #pragma unroll
        for (int j = 0; j < 8; j++) {
            uint4 v = *reinterpret_cast<uint4*>(&Xs[r * 64 + ((base + j * 4) ^ s)]);
            *reinterpret_cast<uint4*>(dst + j * 8) = v;
        }
    }
}

// ---------------------------------------------------------------------------
// Kernel 2 (measured 39us): one warp per node. In-block adj dtype detect,
// softmax(leaky_relu(e)), LDG.128 gather (half-warps on alternate rows), elu.
// ---------------------------------------------------------------------------
__global__ __launch_bounds__(256)
void attn_out_kernel(const int* __restrict__ adj32,
                     float* __restrict__ out)
{
    __shared__ int s_is64;
    const int tid  = threadIdx.x;
    const int lane = tid & 31;

    // detect: adj is int64 iff odd 32-bit words are all zero (values < 2^31)
    if (tid < 32) {
        const int bad = (adj32[2 * tid + 1] != 0) | (adj32[2 * tid + 65] != 0);
        const unsigned mm = __ballot_sync(0xffffffffu, bad);
        if (tid == 0) s_is64 = (mm == 0u);
    }
    __syncthreads();
    const int is64 = s_is64;

    const int warp = (blockIdx.x * blockDim.x + tid) >> 5;   // < NROWS by construction
    const int b = warp / L;
    const size_t nodebase = (size_t)b * L;

    int   idx = 0;
    float e   = -INFINITY;
    if (lane < D) {
        const size_t ei = (size_t)warp * D + lane;
        int raw;
        if (is64) {
            long long v = ((const long long*)adj32)[ei];   // single LDG.64
            raw = (int)v;
        } else {
            raw = adj32[ei];
        }
        raw = raw < 0 ? 0 : (raw >= L ? L - 1 : raw); // defensive clamp
        idx = raw;
        e   = g_s1[nodebase + idx];
    }
    const int idx0 = __shfl_sync(0xffffffffu, idx, 0);
    const float s2v = g_s2[nodebase + idx0];
    if (lane < D) {
        e += s2v;
        e = (e >= 0.f) ? e : LRELU_ALPHA * e;
    }

    float m = e;
    #pragma unroll
    for (int o = 16; o > 0; o >>= 1) m = fmaxf(m, __shfl_xor_sync(0xffffffffu, m, o));
    float p = (lane < D) ? __expf(e - m) : 0.f;
    float s = p;
    #pragma unroll
    for (int o = 16; o > 0; o >>= 1) s += __shfl_xor_sync(0xffffffffu, s, o);
    const float attn = p / s;

    // gather: 8 x LDG.128 per warp (2 rows per iteration via half-warps)
    const int li = lane & 15;
    const int h  = lane >> 4;
    const __half* yb = g_yh + nodebase * F;
    float acc[8];
    #pragma unroll
    for (int j = 0; j < 8; j++) acc[j] = 0.f;

    #pragma unroll
    for (int it = 0; it < 8; it++) {
        const int   d  = 2 * it + h;
        const int   id = __shfl_sync(0xffffffffu, idx,  d);
        const float wt = __shfl_sync(0xffffffffu, attn, d);
        uint4 raw = *(const uint4*)(yb + (size_t)id * F + li * 8);
        const __half2* hh = reinterpret_cast<const __half2*>(&raw);
        #pragma unroll
        for (int j = 0; j < 4; j++) {
            float2 f2 = __half22float2(hh[j]);
            acc[2 * j]     += wt * f2.x;
            acc[2 * j + 1] += wt * f2.y;
        }
    }
    #pragma unroll
    for (int j = 0; j < 8; j++)
        acc[j] += __shfl_xor_sync(0xffffffffu, acc[j], 16);

    // elu (alpha=1) on the 4 values this lane writes: cols li*8 + h*4 + 0..3
    float4 o4;
    o4.x = acc[h * 4 + 0]; o4.y = acc[h * 4 + 1];
    o4.z = acc[h * 4 + 2]; o4.w = acc[h * 4 + 3];
    o4.x = o4.x > 0.f ? o4.x : (__expf(o4.x) - 1.f);
    o4.y = o4.y > 0.f ? o4.y : (__expf(o4.y) - 1.f);
    o4.z = o4.z > 0.f ? o4.z : (__expf(o4.z) - 1.f);
    o4.w = o4.w > 0.f ? o4.w : (__expf(o4.w) - 1.f);

    *(float4*)(out + (size_t)warp * F + li * 8 + h * 4) = o4;
}

// ---------------------------------------------------------------------------
extern "C" void kernel_launch(void* const* d_in, const int* in_sizes, int n_in,
                              void* d_out, int out_size)
{
    //   x: 10,240,000 f32 | adj: 1,280,000 (i32 or i64) | W: 16,384 f32 | a: 256 f32
    const float* x   = nullptr;
    const int*   adj = nullptr;
    const float* W   = nullptr;
    const float* a   = nullptr;
    for (int i = 0; i < n_in; i++) {
        switch (in_sizes[i]) {
            case NROWS * F: x   = (const float*)d_in[i]; break;
            case NROWS * D: adj = (const int*)d_in[i];   break;
            case F * F:     W   = (const float*)d_in[i]; break;
            case 2 * F:     a   = (const float*)d_in[i]; break;
            default: break;
        }
    }
    float* out = (float*)d_out;

    prep_kernel<<<32, 128>>>(W);
    gemm_scores_kernel<<<NROWS / 64, 128>>>(x, a);
    attn_out_kernel<<<(NROWS * 32) / 256, 256>>>(adj, out);
}

// round 13
// speedup vs baseline: 1.2122x; 1.0309x over previous
#include <cuda_runtime.h>
#include <cuda_fp16.h>
#include <cstdint>
#include <cstddef>

// FixedGraphAttentionLayer: bs=4, L=20000, D=16, Fin=Fout=128
//   y = x @ W per node (linear rewrite), y stored fp16.
//   e[b,l,d] = s1[adj[b,l,d]] + s2[adj[b,l,0]]  (scores from fp32 accumulators)
// prep = W fragment pre-pack. k1 = R7-best HMMA GEMM + fused scores.
// k2 = softmax + HFMA2 fp16-partial gather (fp32 every 4 neighbors) + elu.

#define LRELU_ALPHA 0.2f
static constexpr int BS = 4;
static constexpr int L  = 20000;
static constexpr int D  = 16;
static constexpr int F  = 128;
static constexpr int NROWS = BS * L;   // 80000

__device__ __align__(16) __half g_yh[(size_t)NROWS * F];   // 20.5 MB
__device__ float g_s1[NROWS];
__device__ float g_s2[NROWS];
__device__ __align__(16) uint2 g_Bpack[8 * 16 * 32];       // [kc][nt][lane], 32 KB

// ---------------------------------------------------------------------------
// Prep (32 blocks x 128 threads): pack W into mma.m16n8k16 B fragments (fp16).
//   b0 = {W[k0][n], W[k0+1][n]}, b1 = {W[k0+8][n], W[k0+9][n]},
//   k0 = 16*kc + tg*2, n = 8*nt + g   (g = lane>>2, tg = lane&3)
// ---------------------------------------------------------------------------
__global__ void prep_kernel(const float* __restrict__ W)
{
    const int e = blockIdx.x * 128 + threadIdx.x;  // 0..4095
    const int kc = e >> 9, nt = (e >> 5) & 15, lane = e & 31;
    const int g = lane >> 2, tg = lane & 3;
    const int n = nt * 8 + g, k0 = kc * 16 + tg * 2;
    __half2 b0 = __floats2half2_rn(W[k0 * F + n],       W[(k0 + 1) * F + n]);
    __half2 b1 = __floats2half2_rn(W[(k0 + 8) * F + n], W[(k0 + 9) * F + n]);
    uint2 u;
    u.x = *reinterpret_cast<unsigned*>(&b0);
    u.y = *reinterpret_cast<unsigned*>(&b1);
    g_Bpack[e] = u;
}

// ---------------------------------------------------------------------------
// Kernel 1 (R7-best): y = x @ W via HMMA + fused scores. 128 thr, 64 rows/blk.
// x tile staged fp16 in smem (XOR swizzle), B fragments in smem.
// ---------------------------------------------------------------------------
__global__ __launch_bounds__(128)
void gemm_scores_kernel(const float* __restrict__ x,
                        const float* __restrict__ a)
{
    __shared__ __half2 Xs[64 * 64];   // 16 KB
    __shared__ uint2   Bs[4096];      // 32 KB

    const int tid  = threadIdx.x;
    const int lane = tid & 31;
    const int w    = tid >> 5;
    const int g    = lane >> 2;
    const int tg   = lane & 3;
    const int rowbase = blockIdx.x * 64;

    {
        const uint4* src = (const uint4*)g_Bpack;
        uint4*       dst = (uint4*)Bs;
        #pragma unroll
        for (int i = tid; i < 2048; i += 128) dst[i] = src[i];
    }
    #pragma unroll
    for (int j = tid; j < 4096; j += 128) {
        const int r = j >> 6, kh2 = j & 63;
        float2 v = *(const float2*)(x + (size_t)(rowbase + r) * F + kh2 * 2);
        Xs[r * 64 + (kh2 ^ ((r & 7) * 4))] = __floats2half2_rn(v.x, v.y);
    }
    __syncthreads();

    unsigned Areg[8][4];
    {
        const int r0 = w * 16 + g, r1 = r0 + 8;
        const int s  = g * 4;
        #pragma unroll
        for (int kc = 0; kc < 8; kc++) {
            const int kl = kc * 8 + tg, kh = kl + 4;
            Areg[kc][0] = *reinterpret_cast<unsigned*>(&Xs[r0 * 64 + (kl ^ s)]);
            Areg[kc][1] = *reinterpret_cast<unsigned*>(&Xs[r1 * 64 + (kl ^ s)]);
            Areg[kc][2] = *reinterpret_cast<unsigned*>(&Xs[r0 * 64 + (kh ^ s)]);
            Areg[kc][3] = *reinterpret_cast<unsigned*>(&Xs[r1 * 64 + (kh ^ s)]);
        }
    }

    float acc[16][4];
    #pragma unroll
    for (int nt = 0; nt < 16; nt++)
        #pragma unroll
        for (int q = 0; q < 4; q++) acc[nt][q] = 0.f;

    #pragma unroll
    for (int nt = 0; nt < 16; nt++) {
        #pragma unroll
        for (int kc = 0; kc < 8; kc++) {
            const uint2 b = Bs[kc * 512 + nt * 32 + lane];
            asm volatile(
                "mma.sync.aligned.m16n8k16.row.col.f32.f16.f16.f32 "
                "{%0,%1,%2,%3}, {%4,%5,%6,%7}, {%8,%9}, {%0,%1,%2,%3};"
                : "+f"(acc[nt][0]), "+f"(acc[nt][1]), "+f"(acc[nt][2]), "+f"(acc[nt][3])
                : "r"(Areg[kc][0]), "r"(Areg[kc][1]), "r"(Areg[kc][2]), "r"(Areg[kc][3]),
                  "r"(b.x), "r"(b.y));
        }
    }

    float p1a = 0.f, p1b = 0.f, p2a = 0.f, p2b = 0.f;
    #pragma unroll
    for (int nt = 0; nt < 16; nt++) {
        const float2 a1p = *(const float2*)(a + nt * 8 + tg * 2);
        const float2 a2p = *(const float2*)(a + F + nt * 8 + tg * 2);
        p1a += acc[nt][0] * a1p.x + acc[nt][1] * a1p.y;
        p1b += acc[nt][2] * a1p.x + acc[nt][3] * a1p.y;
        p2a += acc[nt][0] * a2p.x + acc[nt][1] * a2p.y;
        p2b += acc[nt][2] * a2p.x + acc[nt][3] * a2p.y;
    }
    #pragma unroll
    for (int o = 1; o <= 2; o <<= 1) {
        p1a += __shfl_xor_sync(0xffffffffu, p1a, o);
        p1b += __shfl_xor_sync(0xffffffffu, p1b, o);
        p2a += __shfl_xor_sync(0xffffffffu, p2a, o);
        p2b += __shfl_xor_sync(0xffffffffu, p2b, o);
    }
    if (tg == 0) {
        const int r = rowbase + w * 16 + g;
        g_s1[r] = p1a;  g_s2[r] = p2a;
        g_s1[r + 8] = p1b;  g_s2[r + 8] = p2b;
    }

    __syncthreads();
    {
        const int r0 = w * 16 + g;
        const int s  = g * 4;
        #pragma unroll
        for (int nt = 0; nt < 16; nt++) {
            const int c = nt * 4 + tg;
            Xs[r0 * 64 + (c ^ s)]       = __floats2half2_rn(acc[nt][0], acc[nt][1]);
            Xs[(r0 + 8) * 64 + (c ^ s)] = __floats2half2_rn(acc[nt][2], acc[nt][3]);
        }
    }
    __syncthreads();
    {
        const int r = tid >> 1;
        const int s = (r & 7) * 4;
        const int base = (tid & 1) * 32;
        __half* dst = g_yh + (size_t)(rowbase + r) * F + base * 2;
        #pragma unroll
        for (int j = 0; j < 8; j++) {
            uint4 v = *reinterpret_cast<uint4*>(&Xs[r * 64 + ((base + j * 4) ^ s)]);
            *reinterpret_cast<uint4*>(dst + j * 8) = v;
        }
    }
}

// ---------------------------------------------------------------------------
// Kernel 2: one warp per node. In-block adj dtype detect, softmax(leaky_relu),
// HFMA2 fp16-partial gather (convert to fp32 every 4 neighbors), shfl merge,
// elu. Half-warp h covers neighbors d = 2*it + h; lane li covers 8 cols.
// ---------------------------------------------------------------------------
__global__ __launch_bounds__(256)
void attn_out_kernel(const int* __restrict__ adj32,
                     float* __restrict__ out)
{
    __shared__ int s_is64;
    const int tid  = threadIdx.x;
    const int lane = tid & 31;

    if (tid < 32) {
        const int bad = (adj32[2 * tid + 1] != 0) | (adj32[2 * tid + 65] != 0);
        const unsigned mm = __ballot_sync(0xffffffffu, bad);
        if (tid == 0) s_is64 = (mm == 0u);
    }
    __syncthreads();
    const int is64 = s_is64;

    const int warp = (blockIdx.x * blockDim.x + tid) >> 5;
    const int b = warp / L;
    const size_t nodebase = (size_t)b * L;

    int   idx = 0;
    float e   = -INFINITY;
    if (lane < D) {
        const size_t ei = (size_t)warp * D + lane;
        int raw;
        if (is64) {
            long long v = ((const long long*)adj32)[ei];
            raw = (int)v;
        } else {
            raw = adj32[ei];
        }
        raw = raw < 0 ? 0 : (raw >= L ? L - 1 : raw);
        idx = raw;
        e   = g_s1[nodebase + idx];
    }
    const int idx0 = __shfl_sync(0xffffffffu, idx, 0);
    const float s2v = g_s2[nodebase + idx0];
    if (lane < D) {
        e += s2v;
        e = (e >= 0.f) ? e : LRELU_ALPHA * e;
    }

    float m = e;
    #pragma unroll
    for (int o = 16; o > 0; o >>= 1) m = fmaxf(m, __shfl_xor_sync(0xffffffffu, m, o));
    float p = (lane < D) ? __expf(e - m) : 0.f;
    float s = p;
    #pragma unroll
    for (int o = 16; o > 0; o >>= 1) s += __shfl_xor_sync(0xffffffffu, s, o);
    const float attn = p / s;

    // pack this lane's attn weight to half2 once; broadcast packed via shfl
    __half2 attn_h2 = __float2half2_rn(attn);
    const unsigned attn_u = *reinterpret_cast<unsigned*>(&attn_h2);

    const int li = lane & 15;
    const int h  = lane >> 4;
    const __half* yb = g_yh + nodebase * F;

    float acc[8];
    #pragma unroll
    for (int j = 0; j < 8; j++) acc[j] = 0.f;

    #pragma unroll
    for (int grp = 0; grp < 2; grp++) {
        __half2 acch[4];
        #pragma unroll
        for (int j = 0; j < 4; j++) acch[j] = __floats2half2_rn(0.f, 0.f);

        #pragma unroll
        for (int it4 = 0; it4 < 4; it4++) {
            const int it = grp * 4 + it4;
            const int d  = 2 * it + h;
            const int      id  = __shfl_sync(0xffffffffu, idx,    d);
            const unsigned wtu = __shfl_sync(0xffffffffu, attn_u, d);
            const __half2  wt2 = *reinterpret_cast<const __half2*>(&wtu);
            uint4 raw = *(const uint4*)(yb + (size_t)id * F + li * 8);
            const __half2* hh = reinterpret_cast<const __half2*>(&raw);
            #pragma unroll
            for (int j = 0; j < 4; j++)
                acch[j] = __hfma2(hh[j], wt2, acch[j]);
        }
        #pragma unroll
        for (int j = 0; j < 4; j++) {
            float2 f2 = __half22float2(acch[j]);
            acc[2 * j]     += f2.x;
            acc[2 * j + 1] += f2.y;
        }
    }
    #pragma unroll
    for (int j = 0; j < 8; j++)
        acc[j] += __shfl_xor_sync(0xffffffffu, acc[j], 16);

    float4 o4;
    o4.x = acc[h * 4 + 0]; o4.y = acc[h * 4 + 1];
    o4.z = acc[h * 4 + 2]; o4.w = acc[h * 4 + 3];
    o4.x = o4.x > 0.f ? o4.x : (__expf(o4.x) - 1.f);
    o4.y = o4.y > 0.f ? o4.y : (__expf(o4.y) - 1.f);
    o4.z = o4.z > 0.f ? o4.z : (__expf(o4.z) - 1.f);
    o4.w = o4.w > 0.f ? o4.w : (__expf(o4.w) - 1.f);

    *(float4*)(out + (size_t)warp * F + li * 8 + h * 4) = o4;
}

// ---------------------------------------------------------------------------
extern "C" void kernel_launch(void* const* d_in, const int* in_sizes, int n_in,
                              void* d_out, int out_size)
{
    //   x: 10,240,000 f32 | adj: 1,280,000 (i32 or i64) | W: 16,384 f32 | a: 256 f32
    const float* x   = nullptr;
    const int*   adj = nullptr;
    const float* W   = nullptr;
    const float* a   = nullptr;
    for (int i = 0; i < n_in; i++) {
        switch (in_sizes[i]) {
            case NROWS * F: x   = (const float*)d_in[i]; break;
            case NROWS * D: adj = (const int*)d_in[i];   break;
            case F * F:     W   = (const float*)d_in[i]; break;
            case 2 * F:     a   = (const float*)d_in[i]; break;
            default: break;
        }
    }
    float* out = (float*)d_out;

    prep_kernel<<<32, 128>>>(W);
    gemm_scores_kernel<<<NROWS / 64, 128>>>(x, a);
    attn_out_kernel<<<(NROWS * 32) / 256, 256>>>(adj, out);
}

// round 14
// speedup vs baseline: 1.3462x; 1.1106x over previous
#include <cuda_runtime.h>
#include <cuda_fp16.h>
#include <cstdint>
#include <cstddef>

// FixedGraphAttentionLayer: bs=4, L=20000, D=16, Fin=Fout=128
//   y = x @ W per node (linear rewrite), y stored fp16.
//   e[b,l,d] = s1[adj[b,l,d]] + s2[adj[b,l,0]]  (scores from fp32 accumulators)
// prep = W fragment pre-pack. k1 = R7-best HMMA GEMM + fused scores.
// k2 = DUAL-NODE warps: lanes 0-15 node 2w, lanes 16-31 node 2w+1.
//      Dense softmax phase, 32 independent row-gather LDGs per warp.

#define LRELU_ALPHA 0.2f
static constexpr int BS = 4;
static constexpr int L  = 20000;
static constexpr int D  = 16;
static constexpr int F  = 128;
static constexpr int NROWS = BS * L;   // 80000

__device__ __align__(16) __half g_yh[(size_t)NROWS * F];   // 20.5 MB
__device__ float g_s1[NROWS];
__device__ float g_s2[NROWS];
__device__ __align__(16) uint2 g_Bpack[8 * 16 * 32];       // [kc][nt][lane], 32 KB

// ---------------------------------------------------------------------------
// Prep (32 blocks x 128 threads): pack W into mma.m16n8k16 B fragments (fp16).
//   b0 = {W[k0][n], W[k0+1][n]}, b1 = {W[k0+8][n], W[k0+9][n]},
//   k0 = 16*kc + tg*2, n = 8*nt + g   (g = lane>>2, tg = lane&3)
// ---------------------------------------------------------------------------
__global__ void prep_kernel(const float* __restrict__ W)
{
    const int e = blockIdx.x * 128 + threadIdx.x;  // 0..4095
    const int kc = e >> 9, nt = (e >> 5) & 15, lane = e & 31;
    const int g = lane >> 2, tg = lane & 3;
    const int n = nt * 8 + g, k0 = kc * 16 + tg * 2;
    __half2 b0 = __floats2half2_rn(W[k0 * F + n],       W[(k0 + 1) * F + n]);
    __half2 b1 = __floats2half2_rn(W[(k0 + 8) * F + n], W[(k0 + 9) * F + n]);
    uint2 u;
    u.x = *reinterpret_cast<unsigned*>(&b0);
    u.y = *reinterpret_cast<unsigned*>(&b1);
    g_Bpack[e] = u;
}

// ---------------------------------------------------------------------------
// Kernel 1 (R7-best): y = x @ W via HMMA + fused scores. 128 thr, 64 rows/blk.
// x tile staged fp16 in smem (XOR swizzle), B fragments in smem.
// ---------------------------------------------------------------------------
__global__ __launch_bounds__(128)
void gemm_scores_kernel(const float* __restrict__ x,
                        const float* __restrict__ a)
{
    __shared__ __half2 Xs[64 * 64];   // 16 KB
    __shared__ uint2   Bs[4096];      // 32 KB

    const int tid  = threadIdx.x;
    const int lane = tid & 31;
    const int w    = tid >> 5;
    const int g    = lane >> 2;
    const int tg   = lane & 3;
    const int rowbase = blockIdx.x * 64;

    {
        const uint4* src = (const uint4*)g_Bpack;
        uint4*       dst = (uint4*)Bs;
        #pragma unroll
        for (int i = tid; i < 2048; i += 128) dst[i] = src[i];
    }
    #pragma unroll
    for (int j = tid; j < 4096; j += 128) {
        const int r = j >> 6, kh2 = j & 63;
        float2 v = *(const float2*)(x + (size_t)(rowbase + r) * F + kh2 * 2);
        Xs[r * 64 + (kh2 ^ ((r & 7) * 4))] = __floats2half2_rn(v.x, v.y);
    }
    __syncthreads();

    unsigned Areg[8][4];
    {
        const int r0 = w * 16 + g, r1 = r0 + 8;
        const int s  = g * 4;
        #pragma unroll
        for (int kc = 0; kc < 8; kc++) {
            const int kl = kc * 8 + tg, kh = kl + 4;
            Areg[kc][0] = *reinterpret_cast<unsigned*>(&Xs[r0 * 64 + (kl ^ s)]);
            Areg[kc][1] = *reinterpret_cast<unsigned*>(&Xs[r1 * 64 + (kl ^ s)]);
            Areg[kc][2] = *reinterpret_cast<unsigned*>(&Xs[r0 * 64 + (kh ^ s)]);
            Areg[kc][3] = *reinterpret_cast<unsigned*>(&Xs[r1 * 64 + (kh ^ s)]);
        }
    }

    float acc[16][4];
    #pragma unroll
    for (int nt = 0; nt < 16; nt++)
        #pragma unroll
        for (int q = 0; q < 4; q++) acc[nt][q] = 0.f;

    #pragma unroll
    for (int nt = 0; nt < 16; nt++) {
        #pragma unroll
        for (int kc = 0; kc < 8; kc++) {
            const uint2 b = Bs[kc * 512 + nt * 32 + lane];
            asm volatile(
                "mma.sync.aligned.m16n8k16.row.col.f32.f16.f16.f32 "
                "{%0,%1,%2,%3}, {%4,%5,%6,%7}, {%8,%9}, {%0,%1,%2,%3};"
                : "+f"(acc[nt][0]), "+f"(acc[nt][1]), "+f"(acc[nt][2]), "+f"(acc[nt][3])
                : "r"(Areg[kc][0]), "r"(Areg[kc][1]), "r"(Areg[kc][2]), "r"(Areg[kc][3]),
                  "r"(b.x), "r"(b.y));
        }
    }

    float p1a = 0.f, p1b = 0.f, p2a = 0.f, p2b = 0.f;
    #pragma unroll
    for (int nt = 0; nt < 16; nt++) {
        const float2 a1p = *(const float2*)(a + nt * 8 + tg * 2);
        const float2 a2p = *(const float2*)(a + F + nt * 8 + tg * 2);
        p1a += acc[nt][0] * a1p.x + acc[nt][1] * a1p.y;
        p1b += acc[nt][2] * a1p.x + acc[nt][3] * a1p.y;
        p2a += acc[nt][0] * a2p.x + acc[nt][1] * a2p.y;
        p2b += acc[nt][2] * a2p.x + acc[nt][3] * a2p.y;
    }
    #pragma unroll
    for (int o = 1; o <= 2; o <<= 1) {
        p1a += __shfl_xor_sync(0xffffffffu, p1a, o);
        p1b += __shfl_xor_sync(0xffffffffu, p1b, o);
        p2a += __shfl_xor_sync(0xffffffffu, p2a, o);
        p2b += __shfl_xor_sync(0xffffffffu, p2b, o);
    }
    if (tg == 0) {
        const int r = rowbase + w * 16 + g;
        g_s1[r] = p1a;  g_s2[r] = p2a;
        g_s1[r + 8] = p1b;  g_s2[r + 8] = p2b;
    }

    __syncthreads();
    {
        const int r0 = w * 16 + g;
        const int s  = g * 4;
        #pragma unroll
        for (int nt = 0; nt < 16; nt++) {
            const int c = nt * 4 + tg;
            Xs[r0 * 64 + (c ^ s)]       = __floats2half2_rn(acc[nt][0], acc[nt][1]);
            Xs[(r0 + 8) * 64 + (c ^ s)] = __floats2half2_rn(acc[nt][2], acc[nt][3]);
        }
    }
    __syncthreads();
    {
        const int r = tid >> 1;
        const int s = (r & 7) * 4;
        const int base = (tid & 1) * 32;
        __half* dst = g_yh + (size_t)(rowbase + r) * F + base * 2;
        #pragma unroll
        for (int j = 0; j < 8; j++) {
            uint4 v = *reinterpret_cast<uint4*>(&Xs[r * 64 + ((base + j * 4) ^ s)]);
            *reinterpret_cast<uint4*>(dst + j * 8) = v;
        }
    }
}

// ---------------------------------------------------------------------------
// Kernel 2: dual-node warps. Warp wg handles nodes 2*wg (lanes 0-15) and
// 2*wg+1 (lanes 16-31). lane = h*16 + li: h selects node, li = neighbor idx.
// adj load is a dense coalesced 32-wide read (element = wg*32 + lane).
// Softmax within 16-lane groups. Gather: 16 iters x 2 independent LDG.64
// (full warp covers one 256B row per node per iter). fp32 accumulate, elu.
// ---------------------------------------------------------------------------
__global__ __launch_bounds__(256)
void attn_out_kernel(const int* __restrict__ adj32,
                     float* __restrict__ out)
{
    __shared__ int s_is64;
    const int tid  = threadIdx.x;
    const int lane = tid & 31;

    // detect: adj is int64 iff odd 32-bit words are all zero (values < 2^31)
    if (tid < 32) {
        const int bad = (adj32[2 * tid + 1] != 0) | (adj32[2 * tid + 65] != 0);
        const unsigned mm = __ballot_sync(0xffffffffu, bad);
        if (tid == 0) s_is64 = (mm == 0u);
    }
    __syncthreads();
    const int is64 = s_is64;

    const int wg   = (blockIdx.x * blockDim.x + tid) >> 5;   // 0..39999
    const int h    = lane >> 4;          // node selector within warp
    const int li   = lane & 15;          // neighbor index within node
    const int node = wg * 2 + h;         // pairs never straddle a batch (L even)
    const size_t nodebase = (size_t)(node / L) * L;

    // coalesced adj load: element index = node*16 + li = wg*32 + lane
    const size_t ei = (size_t)node * D + li;
    int raw;
    if (is64) {
        long long v = ((const long long*)adj32)[ei];   // single LDG.64
        raw = (int)v;
    } else {
        raw = adj32[ei];
    }
    raw = raw < 0 ? 0 : (raw >= L ? L - 1 : raw);      // defensive clamp
    const int idx = raw;
    float e = g_s1[nodebase + idx];

    // s2 term: neighbor 0 of this node lives in lane h*16
    const int idx0 = __shfl_sync(0xffffffffu, idx, h * 16);
    e += g_s2[nodebase + idx0];
    e = (e >= 0.f) ? e : LRELU_ALPHA * e;              // leaky_relu

    // softmax within the 16-lane group
    float m = e;
    #pragma unroll
    for (int o = 8; o > 0; o >>= 1) m = fmaxf(m, __shfl_xor_sync(0xffffffffu, m, o));
    float p = __expf(e - m);
    float s = p;
    #pragma unroll
    for (int o = 8; o > 0; o >>= 1) s += __shfl_xor_sync(0xffffffffu, s, o);
    const float attn = p / s;

    // gather: 16 iters x 2 rows (node0 + node1), full warp per row (8 B/lane)
    const __half* yb = g_yh + nodebase * F;            // warp-uniform
    float acc0[4], acc1[4];
    #pragma unroll
    for (int j = 0; j < 4; j++) { acc0[j] = 0.f; acc1[j] = 0.f; }

    #pragma unroll
    for (int d = 0; d < D; d++) {
        const int   id0 = __shfl_sync(0xffffffffu, idx,  d);
        const float w0  = __shfl_sync(0xffffffffu, attn, d);
        const int   id1 = __shfl_sync(0xffffffffu, idx,  16 + d);
        const float w1  = __shfl_sync(0xffffffffu, attn, 16 + d);
        uint2 r0 = *(const uint2*)(yb + (size_t)id0 * F + lane * 4);
        uint2 r1 = *(const uint2*)(yb + (size_t)id1 * F + lane * 4);
        const __half2* h0 = reinterpret_cast<const __half2*>(&r0);
        const __half2* h1 = reinterpret_cast<const __half2*>(&r1);
        #pragma unroll
        for (int j = 0; j < 2; j++) {
            float2 f0 = __half22float2(h0[j]);
            float2 f1 = __half22float2(h1[j]);
            acc0[2 * j]     += w0 * f0.x;
            acc0[2 * j + 1] += w0 * f0.y;
            acc1[2 * j]     += w1 * f1.x;
            acc1[2 * j + 1] += w1 * f1.y;
        }
    }

    // elu (alpha=1) + store: lane covers cols lane*4..lane*4+3 of both nodes
    float4 o0, o1;
    o0.x = acc0[0]; o0.y = acc0[1]; o0.z = acc0[2]; o0.w = acc0[3];
    o1.x = acc1[0]; o1.y = acc1[1]; o1.z = acc1[2]; o1.w = acc1[3];
    o0.x = o0.x > 0.f ? o0.x : (__expf(o0.x) - 1.f);
    o0.y = o0.y > 0.f ? o0.y : (__expf(o0.y) - 1.f);
    o0.z = o0.z > 0.f ? o0.z : (__expf(o0.z) - 1.f);
    o0.w = o0.w > 0.f ? o0.w : (__expf(o0.w) - 1.f);
    o1.x = o1.x > 0.f ? o1.x : (__expf(o1.x) - 1.f);
    o1.y = o1.y > 0.f ? o1.y : (__expf(o1.y) - 1.f);
    o1.z = o1.z > 0.f ? o1.z : (__expf(o1.z) - 1.f);
    o1.w = o1.w > 0.f ? o1.w : (__expf(o1.w) - 1.f);

    *(float4*)(out + (size_t)(wg * 2)     * F + lane * 4) = o0;
    *(float4*)(out + (size_t)(wg * 2 + 1) * F + lane * 4) = o1;
}

// ---------------------------------------------------------------------------
extern "C" void kernel_launch(void* const* d_in, const int* in_sizes, int n_in,
                              void* d_out, int out_size)
{
    //   x: 10,240,000 f32 | adj: 1,280,000 (i32 or i64) | W: 16,384 f32 | a: 256 f32
    const float* x   = nullptr;
    const int*   adj = nullptr;
    const float* W   = nullptr;
    const float* a   = nullptr;
    for (int i = 0; i < n_in; i++) {
        switch (in_sizes[i]) {
            case NROWS * F: x   = (const float*)d_in[i]; break;
            case NROWS * D: adj = (const int*)d_in[i];   break;
            case F * F:     W   = (const float*)d_in[i]; break;
            case 2 * F:     a   = (const float*)d_in[i]; break;
            default: break;
        }
    }
    float* out = (float*)d_out;

    prep_kernel<<<32, 128>>>(W);
    gemm_scores_kernel<<<NROWS / 64, 128>>>(x, a);
    // 40000 dual-node warps = 1.28M threads / 256 = 5000 blocks
    attn_out_kernel<<<(NROWS / 2 * 32) / 256, 256>>>(adj, out);
}

// round 16
// speedup vs baseline: 1.3575x; 1.0084x over previous
#include <cuda_runtime.h>
#include <cuda_fp16.h>
#include <cstdint>
#include <cstddef>

// FixedGraphAttentionLayer: bs=4, L=20000, D=16, Fin=Fout=128
//   y = x @ W per node (linear rewrite), y stored fp16.
//   e[b,l,d] = s1[adj[b,l,d]] + s2[adj[b,l,0]]  (scores from fp32 accumulators)
// prep = W fragment pre-pack.
// k1 = HMMA GEMM, 256-thr blocks: warp = (row-group, n-half). 24 warps/SM.
// k2 = dual-node warps (R14-best).
// NOTE: tcgen05 unavailable — harness ptxas targets sm_103 (no 'a' features).

#define LRELU_ALPHA 0.2f
static constexpr int BS = 4;
static constexpr int L  = 20000;
static constexpr int D  = 16;
static constexpr int F  = 128;
static constexpr int NROWS = BS * L;   // 80000

__device__ __align__(16) __half g_yh[(size_t)NROWS * F];   // 20.5 MB
__device__ float g_s1[NROWS];
__device__ float g_s2[NROWS];
__device__ __align__(16) uint2 g_Bpack[8 * 16 * 32];       // [kc][nt][lane], 32 KB

// ---------------------------------------------------------------------------
// Prep (32 blocks x 128 threads): pack W into mma.m16n8k16 B fragments (fp16).
//   b0 = {W[k0][n], W[k0+1][n]}, b1 = {W[k0+8][n], W[k0+9][n]},
//   k0 = 16*kc + tg*2, n = 8*nt + g   (g = lane>>2, tg = lane&3)
// ---------------------------------------------------------------------------
__global__ void prep_kernel(const float* __restrict__ W)
{
    const int e = blockIdx.x * 128 + threadIdx.x;  // 0..4095
    const int kc = e >> 9, nt = (e >> 5) & 15, lane = e & 31;
    const int g = lane >> 2, tg = lane & 3;
    const int n = nt * 8 + g, k0 = kc * 16 + tg * 2;
    __half2 b0 = __floats2half2_rn(W[k0 * F + n],       W[(k0 + 1) * F + n]);
    __half2 b1 = __floats2half2_rn(W[(k0 + 8) * F + n], W[(k0 + 9) * F + n]);
    uint2 u;
    u.x = *reinterpret_cast<unsigned*>(&b0);
    u.y = *reinterpret_cast<unsigned*>(&b1);
    g_Bpack[e] = u;
}

// ---------------------------------------------------------------------------
// Kernel 1: y = x @ W via HMMA + fused scores. 256 threads, 64 rows/block.
// Warp w: row-group rw = w&3 (rows rw*16..+15), n-half nh = w>>2
// (n-tiles nh*8..nh*8+7). 64 MMAs per warp. Score partials per n-half are
// combined through smem (Bs region reused after the MMA phase).
// ---------------------------------------------------------------------------
__global__ __launch_bounds__(256, 3)
void gemm_scores_kernel(const float* __restrict__ x,
                        const float* __restrict__ a)
{
    __shared__ __half2 Xs[64 * 64];   // 16 KB: x tile, then y restage
    __shared__ uint2   Bs[4096];      // 32 KB: [kc][nt][lane]; reused for scores

    const int tid  = threadIdx.x;
    const int lane = tid & 31;
    const int w    = tid >> 5;
    const int rw   = w & 3;           // row group
    const int nh   = w >> 2;          // n half (0..1)
    const int g    = lane >> 2;
    const int tg   = lane & 3;
    const int rowbase = blockIdx.x * 64;

    // copy B fragments (32 KB) global -> smem, coalesced
    {
        const uint4* src = (const uint4*)g_Bpack;
        uint4*       dst = (uint4*)Bs;
        #pragma unroll
        for (int i = tid; i < 2048; i += 256) dst[i] = src[i];
    }
    // load x tile (64x128 fp32) -> fp16 swizzled smem
    #pragma unroll
    for (int j = tid; j < 4096; j += 256) {
        const int r = j >> 6, kh2 = j & 63;
        float2 v = *(const float2*)(x + (size_t)(rowbase + r) * F + kh2 * 2);
        Xs[r * 64 + (kh2 ^ ((r & 7) * 4))] = __floats2half2_rn(v.x, v.y);
    }
    __syncthreads();

    // A fragments for this warp's 16 rows, all 8 k-chunks (32 regs)
    unsigned Areg[8][4];
    {
        const int r0 = rw * 16 + g, r1 = r0 + 8;
        const int s  = g * 4;
        #pragma unroll
        for (int kc = 0; kc < 8; kc++) {
            const int kl = kc * 8 + tg, kh = kl + 4;
            Areg[kc][0] = *reinterpret_cast<unsigned*>(&Xs[r0 * 64 + (kl ^ s)]);
            Areg[kc][1] = *reinterpret_cast<unsigned*>(&Xs[r1 * 64 + (kl ^ s)]);
            Areg[kc][2] = *reinterpret_cast<unsigned*>(&Xs[r0 * 64 + (kh ^ s)]);
            Areg[kc][3] = *reinterpret_cast<unsigned*>(&Xs[r1 * 64 + (kh ^ s)]);
        }
    }

    float acc[8][4];
    #pragma unroll
    for (int nt = 0; nt < 8; nt++)
        #pragma unroll
        for (int q = 0; q < 4; q++) acc[nt][q] = 0.f;

    #pragma unroll
    for (int nt = 0; nt < 8; nt++) {
        #pragma unroll
        for (int kc = 0; kc < 8; kc++) {
            const uint2 b = Bs[kc * 512 + (nh * 8 + nt) * 32 + lane];
            asm volatile(
                "mma.sync.aligned.m16n8k16.row.col.f32.f16.f16.f32 "
                "{%0,%1,%2,%3}, {%4,%5,%6,%7}, {%8,%9}, {%0,%1,%2,%3};"
                : "+f"(acc[nt][0]), "+f"(acc[nt][1]), "+f"(acc[nt][2]), "+f"(acc[nt][3])
                : "r"(Areg[kc][0]), "r"(Areg[kc][1]), "r"(Areg[kc][2]), "r"(Areg[kc][3]),
                  "r"(b.x), "r"(b.y));
        }
    }

    // score partials over this warp's n-half (rows g -> a, g+8 -> b)
    float p1a = 0.f, p1b = 0.f, p2a = 0.f, p2b = 0.f;
    #pragma unroll
    for (int nt = 0; nt < 8; nt++) {
        const float2 a1p = *(const float2*)(a + nh * 64 + nt * 8 + tg * 2);
        const float2 a2p = *(const float2*)(a + F + nh * 64 + nt * 8 + tg * 2);
        p1a += acc[nt][0] * a1p.x + acc[nt][1] * a1p.y;
        p1b += acc[nt][2] * a1p.x + acc[nt][3] * a1p.y;
        p2a += acc[nt][0] * a2p.x + acc[nt][1] * a2p.y;
        p2b += acc[nt][2] * a2p.x + acc[nt][3] * a2p.y;
    }
    #pragma unroll
    for (int o = 1; o <= 2; o <<= 1) {   // reduce over tg quad
        p1a += __shfl_xor_sync(0xffffffffu, p1a, o);
        p1b += __shfl_xor_sync(0xffffffffu, p1b, o);
        p2a += __shfl_xor_sync(0xffffffffu, p2a, o);
        p2b += __shfl_xor_sync(0xffffffffu, p2b, o);
    }

    __syncthreads();   // all Bs reads + cross-warp Xs A-frag reads complete

    // score partials -> smem (reuse retired Bs region): [nh][row_in_block]
    float* s1p = reinterpret_cast<float*>(Bs);        // 128 floats
    float* s2p = s1p + 128;                           // 128 floats
    if (tg == 0) {
        const int r = rw * 16 + g;
        s1p[nh * 64 + r]     = p1a;
        s1p[nh * 64 + r + 8] = p1b;
        s2p[nh * 64 + r]     = p2a;
        s2p[nh * 64 + r + 8] = p2b;
    }

    // restage y (fp16) into Xs: this warp's n-half columns of its 16 rows
    {
        const int r0 = rw * 16 + g;
        const int s  = g * 4;
        #pragma unroll
        for (int nt = 0; nt < 8; nt++) {
            const int c = nh * 32 + nt * 4 + tg;      // half2 col 0..63
            Xs[r0 * 64 + (c ^ s)]       = __floats2half2_rn(acc[nt][0], acc[nt][1]);
            Xs[(r0 + 8) * 64 + (c ^ s)] = __floats2half2_rn(acc[nt][2], acc[nt][3]);
        }
    }
    __syncthreads();

    // coalesced y stores: 4 threads per row, 16B chunks
    {
        const int r    = tid >> 2;              // 0..63
        const int q    = tid & 3;
        const int s    = (r & 7) * 4;
        const int base = q * 16;                // half2 offset
        __half* dst = g_yh + (size_t)(rowbase + r) * F + base * 2;
        #pragma unroll
        for (int j = 0; j < 4; j++) {
            uint4 v = *reinterpret_cast<uint4*>(&Xs[r * 64 + ((base + j * 4) ^ s)]);
            *reinterpret_cast<uint4*>(dst + j * 8) = v;
        }
    }
    // combine n-half score partials and store
    if (tid < 64) {
        g_s1[rowbase + tid] = s1p[tid] + s1p[64 + tid];
        g_s2[rowbase + tid] = s2p[tid] + s2p[64 + tid];
    }
}

// ---------------------------------------------------------------------------
// Kernel 2 (R14-best): dual-node warps. Warp wg: nodes 2wg (lanes 0-15),
// 2wg+1 (lanes 16-31). Dense softmax, 2 independent row-gathers per iter.
// ---------------------------------------------------------------------------
__global__ __launch_bounds__(256)
void attn_out_kernel(const int* __restrict__ adj32,
                     float* __restrict__ out)
{
    __shared__ int s_is64;
    const int tid  = threadIdx.x;
    const int lane = tid & 31;

    if (tid < 32) {
        const int bad = (adj32[2 * tid + 1] != 0) | (adj32[2 * tid + 65] != 0);
        const unsigned mm = __ballot_sync(0xffffffffu, bad);
        if (tid == 0) s_is64 = (mm == 0u);
    }
    __syncthreads();
    const int is64 = s_is64;

    const int wg   = (blockIdx.x * blockDim.x + tid) >> 5;
    const int h    = lane >> 4;
    const int li   = lane & 15;
    const int node = wg * 2 + h;
    const size_t nodebase = (size_t)(node / L) * L;

    const size_t ei = (size_t)node * D + li;
    int raw;
    if (is64) {
        long long v = ((const long long*)adj32)[ei];
        raw = (int)v;
    } else {
        raw = adj32[ei];
    }
    raw = raw < 0 ? 0 : (raw >= L ? L - 1 : raw);
    const int idx = raw;
    float e = g_s1[nodebase + idx];

    const int idx0 = __shfl_sync(0xffffffffu, idx, h * 16);
    e += g_s2[nodebase + idx0];
    e = (e >= 0.f) ? e : LRELU_ALPHA * e;

    float m = e;
    #pragma unroll
    for (int o = 8; o > 0; o >>= 1) m = fmaxf(m, __shfl_xor_sync(0xffffffffu, m, o));
    float p = __expf(e - m);
    float s = p;
    #pragma unroll
    for (int o = 8; o > 0; o >>= 1) s += __shfl_xor_sync(0xffffffffu, s, o);
    const float attn = p / s;

    const __half* yb = g_yh + nodebase * F;
    float acc0[4], acc1[4];
    #pragma unroll
    for (int j = 0; j < 4; j++) { acc0[j] = 0.f; acc1[j] = 0.f; }

    #pragma unroll
    for (int d = 0; d < D; d++) {
        const int   id0 = __shfl_sync(0xffffffffu, idx,  d);
        const float w0  = __shfl_sync(0xffffffffu, attn, d);
        const int   id1 = __shfl_sync(0xffffffffu, idx,  16 + d);
        const float w1  = __shfl_sync(0xffffffffu, attn, 16 + d);
        uint2 r0 = *(const uint2*)(yb + (size_t)id0 * F + lane * 4);
        uint2 r1 = *(const uint2*)(yb + (size_t)id1 * F + lane * 4);
        const __half2* h0 = reinterpret_cast<const __half2*>(&r0);
        const __half2* h1 = reinterpret_cast<const __half2*>(&r1);
        #pragma unroll
        for (int j = 0; j < 2; j++) {
            float2 f0 = __half22float2(h0[j]);
            float2 f1 = __half22float2(h1[j]);
            acc0[2 * j]     += w0 * f0.x;
            acc0[2 * j + 1] += w0 * f0.y;
            acc1[2 * j]     += w1 * f1.x;
            acc1[2 * j + 1] += w1 * f1.y;
        }
    }

    float4 o0, o1;
    o0.x = acc0[0]; o0.y = acc0[1]; o0.z = acc0[2]; o0.w = acc0[3];
    o1.x = acc1[0]; o1.y = acc1[1]; o1.z = acc1[2]; o1.w = acc1[3];
    o0.x = o0.x > 0.f ? o0.x : (__expf(o0.x) - 1.f);
    o0.y = o0.y > 0.f ? o0.y : (__expf(o0.y) - 1.f);
    o0.z = o0.z > 0.f ? o0.z : (__expf(o0.z) - 1.f);
    o0.w = o0.w > 0.f ? o0.w : (__expf(o0.w) - 1.f);
    o1.x = o1.x > 0.f ? o1.x : (__expf(o1.x) - 1.f);
    o1.y = o1.y > 0.f ? o1.y : (__expf(o1.y) - 1.f);
    o1.z = o1.z > 0.f ? o1.z : (__expf(o1.z) - 1.f);
    o1.w = o1.w > 0.f ? o1.w : (__expf(o1.w) - 1.f);

    *(float4*)(out + (size_t)(wg * 2)     * F + lane * 4) = o0;
    *(float4*)(out + (size_t)(wg * 2 + 1) * F + lane * 4) = o1;
}

// ---------------------------------------------------------------------------
extern "C" void kernel_launch(void* const* d_in, const int* in_sizes, int n_in,
                              void* d_out, int out_size)
{
    //   x: 10,240,000 f32 | adj: 1,280,000 (i32 or i64) | W: 16,384 f32 | a: 256 f32
    const float* x   = nullptr;
    const int*   adj = nullptr;
    const float* W   = nullptr;
    const float* a   = nullptr;
    for (int i = 0; i < n_in; i++) {
        switch (in_sizes[i]) {
            case NROWS * F: x   = (const float*)d_in[i]; break;
            case NROWS * D: adj = (const int*)d_in[i];   break;
            case F * F:     W   = (const float*)d_in[i]; break;
            case 2 * F:     a   = (const float*)d_in[i]; break;
            default: break;
        }
    }
    float* out = (float*)d_out;

    prep_kernel<<<32, 128>>>(W);
    gemm_scores_kernel<<<NROWS / 64, 256>>>(x, a);
    attn_out_kernel<<<(NROWS / 2 * 32) / 256, 256>>>(adj, out);
}